// round 7
// baseline (speedup 1.0000x reference)
#include <cuda_runtime.h>
#include <cuda_bf16.h>
#include <cstdint>

// Problem constants
#define Bsz   64
#define Lsz   64
#define Hsz   128
#define Ssz   64
#define INsz  16

// c history: [s][b][h]
__device__ float g_chist[Ssz * Bsz * Hsz];

// ---------------- helpers ----------------
__device__ __forceinline__ uint32_t smem_u32(const void* p) {
    uint32_t a;
    asm("{ .reg .u64 t; cvta.to.shared.u64 t, %1; cvt.u32.u64 %0, t; }"
        : "=r"(a) : "l"(p));
    return a;
}
__device__ __forceinline__ uint32_t mapa_rank(uint32_t laddr, uint32_t rk) {
    uint32_t ra;
    asm("mapa.shared::cluster.u32 %0, %1, %2;" : "=r"(ra) : "r"(laddr), "r"(rk));
    return ra;
}
__device__ __forceinline__ void st_cluster_b64(uint32_t addr, uint64_t v) {
    asm volatile("st.shared::cluster.b64 [%0], %1;" :: "r"(addr), "l"(v) : "memory");
}
__device__ __forceinline__ uint32_t cluster_rank() {
    uint32_t r; asm("mov.u32 %0, %%cluster_ctarank;" : "=r"(r)); return r;
}
__device__ __forceinline__ void cluster_sync() {
    asm volatile("barrier.cluster.arrive.aligned;" ::: "memory");
    asm volatile("barrier.cluster.wait.aligned;" ::: "memory");
}
__device__ __forceinline__ float sigf(float x) {
    return __fdividef(1.0f, 1.0f + __expf(-x));
}
__device__ __forceinline__ float tanh_acc(float x) {
    return __fmaf_rn(2.0f, sigf(2.0f * x), -1.0f);
}
__device__ __forceinline__ uint64_t pack2(float lo, float hi) {
    uint64_t r; asm("mov.b64 %0, {%1, %2};" : "=l"(r) : "f"(lo), "f"(hi)); return r;
}
__device__ __forceinline__ void fma2(uint64_t& d, uint64_t a, uint64_t b) {
    asm("fma.rn.f32x2 %0, %1, %2, %0;" : "+l"(d) : "l"(a), "l"(b));
}
__device__ __forceinline__ void mbar_arrive_remote(uint32_t raddr) {
    asm volatile("mbarrier.arrive.release.cluster.shared::cluster.b64 _, [%0];"
                 :: "r"(raddr) : "memory");
}
__device__ __forceinline__ void mbar_wait(uint32_t addr, uint32_t parity) {
    uint32_t done;
    asm volatile(
        "{\n\t.reg .pred p;\n\t"
        "mbarrier.try_wait.parity.acquire.cluster.shared::cta.b64 p, [%1], %2;\n\t"
        "selp.b32 %0, 1, 0, p;\n\t}"
        : "=r"(done) : "r"(addr), "r"(parity) : "memory");
    if (!done) {
        asm volatile(
            "{\n\t.reg .pred P1;\n\t"
            "WAIT_LOOP_%=:\n\t"
            "mbarrier.try_wait.parity.acquire.cluster.shared::cta.b64 P1, [%0], %1, 0x989680;\n\t"
            "@P1 bra.uni WAIT_DONE_%=;\n\t"
            "bra.uni WAIT_LOOP_%=;\n\t"
            "WAIT_DONE_%=:\n\t}"
            :: "r"(addr), "r"(parity) : "memory");
    }
}

// ---------------- kernel 1: recurrence (dual-pipeline) ----------------
// 64 CTAs = 16 clusters x 4. Cluster ci owns 4 batches:
//   pipeline A: {4ci, 4ci+1},  pipeline B: {4ci+2, 4ci+3}.
// CTA rank r: h-tile [32r, 32r+32) => W cols {g*128 + 32r + hh}.
// W slice in REGISTERS (shared by both pipelines).
// Per loop iteration t: [GEMM_A, reduce_A, update+send_A],
//                       wait_B(t-1), [GEMM_B, ..., send_B], wait_A(t).
// The cross-SM exchange of one pipeline is hidden behind the other's compute.
extern "C" __global__ void __cluster_dims__(4, 1, 1) __launch_bounds__(256, 1)
lstm_recur_kernel(const float* __restrict__ emb,
                  const float* __restrict__ Wg,
                  const float* __restrict__ bg)
{
    __shared__ float2 inpd[2 * 2 * 2 * 256];    // [pipe][buf][b][k] dup pairs (16 KB)
    __shared__ float  gpart[8 * 2 * 128];       // [q][b][jl] shared between pipes (8 KB)
    __shared__ float  gs[2 * 128];              // activated gates (shared)
    __shared__ float  bias_s[128];
    __shared__ __align__(8) uint64_t mbar[2];   // one per pipeline

    const int tid = threadIdx.x;
    const uint32_t r = cluster_rank();
    const int b0 = (blockIdx.x >> 2) * 4;

    const int j4 = tid & 31;
    const int kq = tid >> 5;
    const int jl0 = j4 * 4;

    // ---- W slice to registers, packed as j-pairs ----
    uint64_t wp[64];
    {
        const int jg0 = ((jl0 >> 5) << 7) + (int)(r << 5) + (jl0 & 31);
        #pragma unroll
        for (int kk = 0; kk < 32; ++kk) {
            const float4 w4 = *(const float4*)(Wg + (size_t)(kq * 32 + kk) * 512 + jg0);
            wp[2 * kk]     = pack2(w4.x, w4.y);
            wp[2 * kk + 1] = pack2(w4.z, w4.w);
        }
    }
    if (tid < 128)
        bias_s[tid] = bg[((tid >> 5) << 7) + (int)(r << 5) + (tid & 31)];

    // ---- init inpd[p][0] = dup([emb[:,0,:], zeros]) for both pipelines ----
    for (int idx = tid; idx < 1024; idx += 256) {
        int p = idx >> 9, bb = (idx >> 8) & 1, k = idx & 255;
        float v = (k < 128) ? emb[(size_t)(b0 + p * 2 + bb) * (Lsz * Hsz) + k] : 0.0f;
        inpd[(p * 4 + bb) * 256 + k] = make_float2(v, v);  // buf 0
    }
    if (tid == 0) {
        asm volatile("mbarrier.init.shared.b64 [%0], 256;"
                     :: "r"(smem_u32(&mbar[0])) : "memory");
        asm volatile("mbarrier.init.shared.b64 [%0], 256;"
                     :: "r"(smem_u32(&mbar[1])) : "memory");
    }
    __syncthreads();
    cluster_sync();   // mbar init + inpd visible cluster-wide before any remote op

    // ---- remote addresses (mapa is offset-preserving; scatter rank = tid>>6) ----
    const uint32_t pr    = (uint32_t)(tid >> 6);     // target rank for scatter
    const uint32_t mbarA_l = smem_u32(&mbar[0]);
    const uint32_t inpd_l  = smem_u32(&inpd[0]);
    const uint32_t mbarA_r = mapa_rank(mbarA_l, pr);
    const uint32_t inpd_r  = mapa_rank(inpd_l, pr);

    const int v  = tid & 63;       // scatter value id
    const int ub = v >> 5;         // batch within pipe
    const int hh = v & 31;         // h within our tile
    const int hglob = (int)(r << 5) + hh;

    float c_old[2] = {0.0f, 0.0f};   // per-pipeline c state (replicated over pr groups)

    uint64_t* gp8 = (uint64_t*)gpart;
    const uint32_t gb = (uint32_t)(kq * 128 + (jl0 >> 1));

    for (int t = 0; t < Ssz; ++t) {
        const int cur = t & 1, nxt = cur ^ 1;

        #pragma unroll
        for (int p = 0; p < 2; ++p) {
            // wait for this pipe's previous exchange (B only; A waited at loop end)
            if (p == 1 && t > 0)
                mbar_wait(mbarA_l + 8, (uint32_t)((t - 1) & 1));

            // ---- GEMM: 32 k-iters, 4 f32x2 FMA ----
            const uint64_t* ip0 = (const uint64_t*)(inpd + (p * 2 + cur) * 512) + kq * 32;
            const uint64_t* ip1 = ip0 + 256;
            uint64_t a00 = 0, a01 = 0, a10 = 0, a11 = 0;
            #pragma unroll
            for (int kk = 0; kk < 32; ++kk) {
                uint64_t x0 = ip0[kk];
                uint64_t x1 = ip1[kk];
                fma2(a00, wp[2 * kk], x0);
                fma2(a01, wp[2 * kk + 1], x0);
                fma2(a10, wp[2 * kk], x1);
                fma2(a11, wp[2 * kk + 1], x1);
            }
            gp8[gb]          = a00;
            gp8[gb + 1]      = a01;
            gp8[gb + 64]     = a10;
            gp8[gb + 64 + 1] = a11;
            __syncthreads();

            // ---- reduce + activation: one thread per (b, gate-col) ----
            {
                const int bb = tid >> 7, jl = tid & 127;
                float vv = bias_s[jl];
                #pragma unroll
                for (int q = 0; q < 8; ++q)
                    vv += gpart[q * 256 + bb * 128 + jl];
                gs[bb * 128 + jl] = (jl < 96) ? sigf(vv) : tanh_acc(vv);
            }
            __syncthreads();

            // ---- combine + scatter: all 256 threads (redundant over 4 rank-groups) ----
            {
                const float* g = gs + ub * 128;
                float f = g[hh], iv = g[32 + hh], ov = g[64 + hh], cd = g[96 + hh];
                float cn = __fmaf_rn(f, c_old[p], iv * cd);
                float hn = ov * tanh_acc(cn);
                c_old[p] = cn;

                if (pr == 0)
                    g_chist[((t << 6) + (b0 + p * 2 + ub)) * 128 + hglob] = cn;

                if (t < Ssz - 1) {
                    const uint32_t off_c =
                        (uint32_t)(((p * 2 + nxt) * 2 + ub) * 256 + hglob) * 8u;
                    st_cluster_b64(inpd_r + off_c, pack2(cn, cn));
                    st_cluster_b64(inpd_r + off_c + 128 * 8, pack2(hn, hn));
                    mbar_arrive_remote(mbarA_r + (uint32_t)(p * 8));
                }
            }
        }
        // wait for A's exchange sent this iteration (hidden behind B phase)
        if (t < Ssz - 1)
            mbar_wait(mbarA_l, (uint32_t)(t & 1));
    }
}

// ---------------- kernel 2: projection + broadcast write ----------------
extern "C" __global__ void __launch_bounds__(128)
proj_kernel(const float* __restrict__ Wlin,
            const float* __restrict__ blin,
            float* __restrict__ out)
{
    __shared__ float sc[128];
    __shared__ float pred[8][16];
    __shared__ float pv[16];

    const int bs = blockIdx.x;
    const int b = bs >> 6, s = bs & 63;
    const int tid = threadIdx.x;

    sc[tid] = g_chist[((s << 6) + b) * 128 + tid];
    __syncthreads();

    const int o = tid & 15, hq = tid >> 4;
    float acc = 0.0f;
    #pragma unroll
    for (int u = 0; u < 16; ++u) {
        int h = (hq << 4) + u;
        acc = __fmaf_rn(sc[h], Wlin[h * 16 + o], acc);
    }
    pred[hq][o] = acc;
    __syncthreads();

    if (tid < 16) {
        float v = blin[tid];
        #pragma unroll
        for (int q = 0; q < 8; ++q) v += pred[q][tid];
        pv[tid] = v;
    }
    __syncthreads();

    float4* dst = (float4*)(out + 262144) + (size_t)((b << 12) + (s << 6)) * 4;
    int c0 = (tid & 3) << 2;
    float4 val = make_float4(pv[c0], pv[c0 + 1], pv[c0 + 2], pv[c0 + 3]);
    dst[tid]       = val;
    dst[tid + 128] = val;
}

// ---------------- kernel 3: trip passthrough copy ----------------
extern "C" __global__ void __launch_bounds__(256)
trip_copy_kernel(const float4* __restrict__ in, float4* __restrict__ out)
{
    int i = blockIdx.x * 256 + threadIdx.x;
    out[i] = in[i];
}

// ---------------- launch ----------------
extern "C" void kernel_launch(void* const* d_in, const int* in_sizes, int n_in,
                              void* d_out, int out_size)
{
    const float* trip = (const float*)d_in[0];
    // d_in[1] = valid_len (unused by reference)
    const float* emb  = (const float*)d_in[2];
    const float* Wg   = (const float*)d_in[3];
    const float* bg   = (const float*)d_in[4];
    const float* Wl   = (const float*)d_in[5];
    const float* bl   = (const float*)d_in[6];
    float* out = (float*)d_out;

    lstm_recur_kernel<<<64, 256>>>(emb, Wg, bg);
    proj_kernel<<<Bsz * Ssz, 128>>>(Wl, bl, out);
    trip_copy_kernel<<<256, 256>>>((const float4*)trip, (float4*)out);
}